// round 4
// baseline (speedup 1.0000x reference)
#include <cuda_runtime.h>

// DendriticBranchLayerSparse
//   x:           [1024, 32768] f32   (d_in[0])   viewed as [1024, 8192] float4
//   t:           [1024]        f32   (d_in[1])
//   weight_vals: [32768]       f32   (d_in[2])   viewed as [8192] float4
//   t_weights:   [8192, 1]     f32   (d_in[3])
//   out:         [1024, 8192]  f32
//
// out[b,o] = dot(w4[o], x4[b,o]) + t[b]*t_weights[o]
//
// R=32 rows/thread -> 1024 blocks = exactly ONE wave on 148 SMs (no tail).
// Output stores use st.global.cs (evict-first) so the 32MB output doesn't
// evict the ~128MB x stream from the 126MB L2 across graph replays.

static constexpr int BATCH   = 1024;
static constexpr int NUM_OUT = 8192;
static constexpr int R       = 32;   // batch rows per thread

__global__ void __launch_bounds__(256)
dendritic_kernel(const float4* __restrict__ x4,
                 const float*  __restrict__ t,
                 const float4* __restrict__ w4,
                 const float*  __restrict__ tw,
                 float* __restrict__ out)
{
    int idx = blockIdx.x * blockDim.x + threadIdx.x;
    int o  = idx & (NUM_OUT - 1);       // output column (lane-consecutive -> coalesced)
    int rg = idx >> 13;                 // row-group index
    int b0 = rg * R;

    // Weights: loaded once, reused for R=32 rows
    const float4 w   = __ldg(&w4[o]);
    const float  twv = __ldg(&tw[o]);

    const float4* xrow = x4 + (size_t)b0 * NUM_OUT + o;
    float*        orow = out + (size_t)b0 * NUM_OUT + o;

    #pragma unroll 8
    for (int r = 0; r < R; r++) {
        float4 xv = xrow[(size_t)r * NUM_OUT];
        float  tb = t[b0 + r];                    // warp-uniform broadcast, L1/L2 hit
        float  res = fmaf(xv.x, w.x,
                     fmaf(xv.y, w.y,
                     fmaf(xv.z, w.z,
                     fmaf(xv.w, w.w, tb * twv))));
        __stcs(&orow[(size_t)r * NUM_OUT], res);  // evict-first: keep L2 for x
    }
}

extern "C" void kernel_launch(void* const* d_in, const int* in_sizes, int n_in,
                              void* d_out, int out_size)
{
    const float4* x4 = (const float4*)d_in[0];
    const float*  t  = (const float*) d_in[1];
    const float4* w4 = (const float4*)d_in[2];
    const float*  tw = (const float*) d_in[3];
    float* out = (float*)d_out;

    const int total_threads = NUM_OUT * (BATCH / R);  // 8192 * 32 = 262144
    const int block = 256;
    const int grid  = total_threads / block;          // 1024 blocks = 1 wave

    dendritic_kernel<<<grid, block>>>(x4, t, w4, tw, out);
}